// round 13
// baseline (speedup 1.0000x reference)
#include <cuda_runtime.h>

#define TPB 64
// Per-sample smem stride 51 (odd => conflict-free rows). Euler of bone i at
// slots 3i..3i+2; joint i+1 written at its NATURAL slot 3(i+1) (bone i+1's
// euler prefetched one bone ahead). Root -> slots 0..2. After compute the
// buffer equals the packed output layout exactly (linear float4 copy out).
#define EOSTR 51

// One FK bone step using only the third-row vector of the accumulated
// rotation:  v' = ((v @ Rx) @ Ry) @ Rz,  pos' = pos + L * v'.
// (Reference uses only row 2 of M; rows propagate independently under
//  right-multiplication, so the full 3x3 compose is never needed.)
__device__ __forceinline__ void bone_step(
    float& vx, float& vy, float& vz,
    float& px, float& py, float& pz,
    float ax, float ay, float az, float Lb)
{
    float sa, ca, sb, cb, sc, cc;
    __sincosf(ax, &sa, &ca);
    __sincosf(ay, &sb, &cb);
    __sincosf(az, &sc, &cc);
    // v @ Rx : (vx, vy*ca + vz*sa, vz*ca - vy*sa)
    float t1 = fmaf(vy, ca,  vz * sa);
    float t2 = fmaf(vz, ca, -vy * sa);
    // @ Ry : (vx*cb - t2*sb, t1, vx*sb + t2*cb)
    float u0 = fmaf(vx, cb, -t2 * sb);
    float u2 = fmaf(vx, sb,  t2 * cb);
    // @ Rz : (u0*cc + t1*sc, t1*cc - u0*sc, u2)
    vx = fmaf(u0, cc,  t1 * sc);
    vy = fmaf(t1, cc, -u0 * sc);
    vz = u2;
    px = fmaf(Lb, vx, px); py = fmaf(Lb, vy, py); pz = fmaf(Lb, vz, pz);
}

#define PREFETCH(b) nx = eo[3*(b)]; ny = eo[3*(b)+1]; nz = eo[3*(b)+2]
#define STOREJ(j) eo[3*(j)] = px; eo[3*(j)+1] = py; eo[3*(j)+2] = pz
#define SHIFT() ax = nx; ay = ny; az = nz
#define RESET_ROOT() vx = 0.f; vy = 0.f; vz = 1.f; px = 0.f; py = 0.f; pz = 0.f
#define FROM_J8() vx = v8x; vy = v8y; vz = v8z; px = p8x; py = p8y; pz = p8z

__device__ __forceinline__ void fk_compute(float* eo, const float L[16]) {
    float ax = eo[0], ay = eo[1], az = eo[2];
    float nx, ny, nz;
    float vx, vy, vz, px, py, pz;
    float v8x, v8y, v8z, p8x, p8y, p8z;

    // leg 1: bones 0,1,2 -> joints 1,2,3
    PREFETCH(1); RESET_ROOT();
    bone_step(vx,vy,vz,px,py,pz, ax,ay,az, L[0]);  STOREJ(1);  SHIFT();
    PREFETCH(2);
    bone_step(vx,vy,vz,px,py,pz, ax,ay,az, L[1]);  STOREJ(2);  SHIFT();
    PREFETCH(3);
    bone_step(vx,vy,vz,px,py,pz, ax,ay,az, L[2]);  STOREJ(3);  SHIFT();

    // leg 2: bones 3,4,5 -> joints 4,5,6
    PREFETCH(4); RESET_ROOT();
    bone_step(vx,vy,vz,px,py,pz, ax,ay,az, L[3]);  STOREJ(4);  SHIFT();
    PREFETCH(5);
    bone_step(vx,vy,vz,px,py,pz, ax,ay,az, L[4]);  STOREJ(5);  SHIFT();
    PREFETCH(6);
    bone_step(vx,vy,vz,px,py,pz, ax,ay,az, L[5]);  STOREJ(6);  SHIFT();

    // spine: bone 6 (0->7), bone 7 (7->8)
    PREFETCH(7); RESET_ROOT();
    bone_step(vx,vy,vz,px,py,pz, ax,ay,az, L[6]);  STOREJ(7);  SHIFT();
    PREFETCH(8);
    bone_step(vx,vy,vz,px,py,pz, ax,ay,az, L[7]);  STOREJ(8);
    v8x = vx; v8y = vy; v8z = vz; p8x = px; p8y = py; p8z = pz;
    SHIFT();

    // head: bones 8 (8->9), 9 (9->10)
    PREFETCH(9);
    bone_step(vx,vy,vz,px,py,pz, ax,ay,az, L[8]);  STOREJ(9);  SHIFT();
    PREFETCH(10);
    bone_step(vx,vy,vz,px,py,pz, ax,ay,az, L[9]);  STOREJ(10); SHIFT();

    // arm A: bones 10,11,12 (8->11->12->13)
    PREFETCH(11); FROM_J8();
    bone_step(vx,vy,vz,px,py,pz, ax,ay,az, L[10]); STOREJ(11); SHIFT();
    PREFETCH(12);
    bone_step(vx,vy,vz,px,py,pz, ax,ay,az, L[11]); STOREJ(12); SHIFT();
    PREFETCH(13);
    bone_step(vx,vy,vz,px,py,pz, ax,ay,az, L[12]); STOREJ(13); SHIFT();

    // arm B: bones 13,14,15 (8->14->15->16)
    PREFETCH(14); FROM_J8();
    bone_step(vx,vy,vz,px,py,pz, ax,ay,az, L[13]); STOREJ(14); SHIFT();
    PREFETCH(15);
    bone_step(vx,vy,vz,px,py,pz, ax,ay,az, L[14]); STOREJ(15); SHIFT();
    bone_step(vx,vy,vz,px,py,pz, ax,ay,az, L[15]); STOREJ(16);

    eo[0] = 0.f; eo[1] = 0.f; eo[2] = 0.f;   // root joint
}

extern "C" __global__ void __launch_bounds__(TPB, 16)
fk_kernel(const float* __restrict__ euler, const float* __restrict__ blen,
          float* __restrict__ out, int N)
{
    extern __shared__ float sm[];
    float* s_eo = sm;                      // TPB * EOSTR

    const int t    = threadIdx.x;
    const int base = blockIdx.x * TPB;
    const int ns   = min(TPB, N - base);
    const bool full = (ns == TPB);

    // ---- euler staging: float4 LDG (12 independent loads -> high MLP),
    //      phased STS into conflict-free odd-stride rows ----
    {
        const float4* ge = (const float4*)(euler + (size_t)base * 48);
        if (full) {
#pragma unroll
            for (int k = 0; k < 12; k++) {
                int i = t + k * TPB;
                float4 v = ge[i];
                int s = i / 12, r = i - s * 12;
                float* p = s_eo + s * EOSTR + r * 4;
                p[0] = v.x; p[1] = v.y; p[2] = v.z; p[3] = v.w;
            }
        } else {
            const int ne4 = ns * 12;
            for (int i = t; i < ne4; i += TPB) {
                float4 v = ge[i];
                int s = i / 12, r = i - s * 12;
                float* p = s_eo + s * EOSTR + r * 4;
                p[0] = v.x; p[1] = v.y; p[2] = v.z; p[3] = v.w;
            }
        }
    }

    // ---- bone lengths: direct per-thread float4 LDG (adds MLP, no smem) ----
    float L[16];
    if (t < ns) {
        const float4* gb = (const float4*)(blen + (size_t)(base + t) * 16);
        float4 a = gb[0], b = gb[1], c = gb[2], d = gb[3];
        L[0]=a.x;  L[1]=a.y;  L[2]=a.z;  L[3]=a.w;
        L[4]=b.x;  L[5]=b.y;  L[6]=b.z;  L[7]=b.w;
        L[8]=c.x;  L[9]=c.y;  L[10]=c.z; L[11]=c.w;
        L[12]=d.x; L[13]=d.y; L[14]=d.z; L[15]=d.w;
    }
    __syncthreads();

    // ---- per-sample FK: outputs land at natural slots -> smem == out layout ----
    if (t < ns) {
        fk_compute(s_eo + t * EOSTR, L);
    }
    __syncthreads();

    // ---- store: pure linear copy, float4, zero index math ----
    {
        float* go = out + (size_t)base * 51;
        if (full) {
            // 51*64 = 3264 floats = 816 float4 = 12*64 + 48
            float4* go4 = (float4*)go;
            const float4* se4 = (const float4*)s_eo;
#pragma unroll
            for (int k = 0; k < 12; k++)
                go4[t + k * TPB] = se4[t + k * TPB];
            if (t < 48)
                go4[t + 12 * TPB] = se4[t + 12 * TPB];
        } else {
            const int nf = ns * 51;
            for (int g = t; g < nf; g += TPB)
                go[g] = s_eo[g];
        }
    }
}

extern "C" void kernel_launch(void* const* d_in, const int* in_sizes, int n_in,
                              void* d_out, int out_size)
{
    const float* euler = (const float*)d_in[0];   // (N,16,3) f32
    const float* blen  = (const float*)d_in[1];   // (N,16,1) f32
    float* out = (float*)d_out;                   // (N,17,3) f32

    const int N = in_sizes[0] / 48;
    const int grid = (N + TPB - 1) / TPB;
    const size_t smem = (size_t)TPB * EOSTR * sizeof(float); // 13,056 B -> 16 blocks/SM

    cudaFuncSetAttribute(fk_kernel, cudaFuncAttributeMaxDynamicSharedMemorySize, (int)smem);
    cudaFuncSetAttribute(fk_kernel, cudaFuncAttributePreferredSharedMemoryCarveout,
                         cudaSharedmemCarveoutMaxShared);
    fk_kernel<<<grid, TPB, smem>>>(euler, blen, out, N);
}

// round 14
// speedup vs baseline: 1.0616x; 1.0616x over previous
#include <cuda_runtime.h>
#include <cstdint>

#define TPB 64
// Per-sample smem stride 51 (odd => conflict-free rows). Euler of bone i at
// slots 3i..3i+2; joint i+1 written at its NATURAL slot 3(i+1) (bone i+1's
// euler prefetched one bone ahead). Root -> slots 0..2. After compute the
// buffer equals the packed output layout exactly -> single bulk-copy out.
#define EOSTR 51
#define TILE_BYTES (TPB * EOSTR * 4)   // 13056, multiple of 16

// One FK bone step using only the third-row vector of the accumulated
// rotation:  v' = ((v @ Rx) @ Ry) @ Rz,  pos' = pos + L * v'.
__device__ __forceinline__ void bone_step(
    float& vx, float& vy, float& vz,
    float& px, float& py, float& pz,
    float ax, float ay, float az, float Lb)
{
    float sa, ca, sb, cb, sc, cc;
    __sincosf(ax, &sa, &ca);
    __sincosf(ay, &sb, &cb);
    __sincosf(az, &sc, &cc);
    float t1 = fmaf(vy, ca,  vz * sa);
    float t2 = fmaf(vz, ca, -vy * sa);
    float u0 = fmaf(vx, cb, -t2 * sb);
    float u2 = fmaf(vx, sb,  t2 * cb);
    vx = fmaf(u0, cc,  t1 * sc);
    vy = fmaf(t1, cc, -u0 * sc);
    vz = u2;
    px = fmaf(Lb, vx, px); py = fmaf(Lb, vy, py); pz = fmaf(Lb, vz, pz);
}

#define PREFETCH(b) nx = eo[3*(b)]; ny = eo[3*(b)+1]; nz = eo[3*(b)+2]
#define STOREJ(j) eo[3*(j)] = px; eo[3*(j)+1] = py; eo[3*(j)+2] = pz
#define SHIFT() ax = nx; ay = ny; az = nz
#define RESET_ROOT() vx = 0.f; vy = 0.f; vz = 1.f; px = 0.f; py = 0.f; pz = 0.f
#define FROM_J8() vx = v8x; vy = v8y; vz = v8z; px = p8x; py = p8y; pz = p8z

__device__ __forceinline__ void fk_compute(float* eo, const float L[16]) {
    float ax = eo[0], ay = eo[1], az = eo[2];
    float nx, ny, nz;
    float vx, vy, vz, px, py, pz;
    float v8x, v8y, v8z, p8x, p8y, p8z;

    // leg 1: bones 0,1,2 -> joints 1,2,3
    PREFETCH(1); RESET_ROOT();
    bone_step(vx,vy,vz,px,py,pz, ax,ay,az, L[0]);  STOREJ(1);  SHIFT();
    PREFETCH(2);
    bone_step(vx,vy,vz,px,py,pz, ax,ay,az, L[1]);  STOREJ(2);  SHIFT();
    PREFETCH(3);
    bone_step(vx,vy,vz,px,py,pz, ax,ay,az, L[2]);  STOREJ(3);  SHIFT();

    // leg 2: bones 3,4,5 -> joints 4,5,6
    PREFETCH(4); RESET_ROOT();
    bone_step(vx,vy,vz,px,py,pz, ax,ay,az, L[3]);  STOREJ(4);  SHIFT();
    PREFETCH(5);
    bone_step(vx,vy,vz,px,py,pz, ax,ay,az, L[4]);  STOREJ(5);  SHIFT();
    PREFETCH(6);
    bone_step(vx,vy,vz,px,py,pz, ax,ay,az, L[5]);  STOREJ(6);  SHIFT();

    // spine: bone 6 (0->7), bone 7 (7->8)
    PREFETCH(7); RESET_ROOT();
    bone_step(vx,vy,vz,px,py,pz, ax,ay,az, L[6]);  STOREJ(7);  SHIFT();
    PREFETCH(8);
    bone_step(vx,vy,vz,px,py,pz, ax,ay,az, L[7]);  STOREJ(8);
    v8x = vx; v8y = vy; v8z = vz; p8x = px; p8y = py; p8z = pz;
    SHIFT();

    // head: bones 8 (8->9), 9 (9->10)
    PREFETCH(9);
    bone_step(vx,vy,vz,px,py,pz, ax,ay,az, L[8]);  STOREJ(9);  SHIFT();
    PREFETCH(10);
    bone_step(vx,vy,vz,px,py,pz, ax,ay,az, L[9]);  STOREJ(10); SHIFT();

    // arm A: bones 10,11,12 (8->11->12->13)
    PREFETCH(11); FROM_J8();
    bone_step(vx,vy,vz,px,py,pz, ax,ay,az, L[10]); STOREJ(11); SHIFT();
    PREFETCH(12);
    bone_step(vx,vy,vz,px,py,pz, ax,ay,az, L[11]); STOREJ(12); SHIFT();
    PREFETCH(13);
    bone_step(vx,vy,vz,px,py,pz, ax,ay,az, L[12]); STOREJ(13); SHIFT();

    // arm B: bones 13,14,15 (8->14->15->16)
    PREFETCH(14); FROM_J8();
    bone_step(vx,vy,vz,px,py,pz, ax,ay,az, L[13]); STOREJ(14); SHIFT();
    PREFETCH(15);
    bone_step(vx,vy,vz,px,py,pz, ax,ay,az, L[14]); STOREJ(15); SHIFT();
    bone_step(vx,vy,vz,px,py,pz, ax,ay,az, L[15]); STOREJ(16);

    eo[0] = 0.f; eo[1] = 0.f; eo[2] = 0.f;   // root joint
}

extern "C" __global__ void __launch_bounds__(TPB, 16)
fk_kernel(const float* __restrict__ euler, const float* __restrict__ blen,
          float* __restrict__ out, int N)
{
    extern __shared__ float sm[];
    float* s_eo = sm;                      // TPB * EOSTR

    const int t    = threadIdx.x;
    const int base = blockIdx.x * TPB;
    const int ns   = min(TPB, N - base);
    const bool full = (ns == TPB);

    // ---- euler staging: float4 LDG (12 independent loads -> high MLP),
    //      phased STS into conflict-free odd-stride rows ----
    {
        const float4* ge = (const float4*)(euler + (size_t)base * 48);
        if (full) {
#pragma unroll
            for (int k = 0; k < 12; k++) {
                int i = t + k * TPB;
                float4 v = ge[i];
                int s = i / 12, r = i - s * 12;
                float* p = s_eo + s * EOSTR + r * 4;
                p[0] = v.x; p[1] = v.y; p[2] = v.z; p[3] = v.w;
            }
        } else {
            const int ne4 = ns * 12;
            for (int i = t; i < ne4; i += TPB) {
                float4 v = ge[i];
                int s = i / 12, r = i - s * 12;
                float* p = s_eo + s * EOSTR + r * 4;
                p[0] = v.x; p[1] = v.y; p[2] = v.z; p[3] = v.w;
            }
        }
    }

    // ---- bone lengths: direct per-thread float4 LDG (adds MLP, no smem) ----
    float L[16];
    if (t < ns) {
        const float4* gb = (const float4*)(blen + (size_t)(base + t) * 16);
        float4 a = gb[0], b = gb[1], c = gb[2], d = gb[3];
        L[0]=a.x;  L[1]=a.y;  L[2]=a.z;  L[3]=a.w;
        L[4]=b.x;  L[5]=b.y;  L[6]=b.z;  L[7]=b.w;
        L[8]=c.x;  L[9]=c.y;  L[10]=c.z; L[11]=c.w;
        L[12]=d.x; L[13]=d.y; L[14]=d.z; L[15]=d.w;
    }
    __syncthreads();

    // ---- per-sample FK: outputs land at natural slots -> smem == out layout ----
    if (t < ns) {
        fk_compute(s_eo + t * EOSTR, L);
    }
    __syncthreads();

    // ---- store: one async bulk copy smem -> gmem (13,056 B), issued by t0.
    //      Replaces ~104 LDS.128 + 104 STG.128 wavefronts per block. ----
    if (full) {
        if (t == 0) {
            // order generic-proxy STS (compute) before async-proxy bulk read
            asm volatile("fence.proxy.async.shared::cta;" ::: "memory");
            unsigned int sa = (unsigned int)__cvta_generic_to_shared(s_eo);
            float* go = out + (size_t)base * 51;
            asm volatile(
                "cp.async.bulk.global.shared::cta.bulk_group [%0], [%1], %2;\n"
                :: "l"(go), "r"(sa), "r"((int)TILE_BYTES) : "memory");
            asm volatile("cp.async.bulk.commit_group;" ::: "memory");
            asm volatile("cp.async.bulk.wait_group 0;" ::: "memory");
        }
    } else {
        float* go = out + (size_t)base * 51;
        const int nf = ns * 51;
        for (int g = t; g < nf; g += TPB)
            go[g] = s_eo[g];
    }
}

extern "C" void kernel_launch(void* const* d_in, const int* in_sizes, int n_in,
                              void* d_out, int out_size)
{
    const float* euler = (const float*)d_in[0];   // (N,16,3) f32
    const float* blen  = (const float*)d_in[1];   // (N,16,1) f32
    float* out = (float*)d_out;                   // (N,17,3) f32

    const int N = in_sizes[0] / 48;
    const int grid = (N + TPB - 1) / TPB;
    const size_t smem = (size_t)TPB * EOSTR * sizeof(float); // 13,056 B -> 16 blocks/SM

    cudaFuncSetAttribute(fk_kernel, cudaFuncAttributeMaxDynamicSharedMemorySize, (int)smem);
    cudaFuncSetAttribute(fk_kernel, cudaFuncAttributePreferredSharedMemoryCarveout,
                         cudaSharedmemCarveoutMaxShared);
    fk_kernel<<<grid, TPB, smem>>>(euler, blen, out, N);
}

// round 16
// speedup vs baseline: 1.0866x; 1.0235x over previous
#include <cuda_runtime.h>
#include <cstdint>

#define TPB 64
#define WSAMP 32                        // samples per warp
// Per-sample smem stride 51 (odd => conflict-free rows). Euler of bone i at
// slots 3i..3i+2; joint i+1 written at its NATURAL slot 3(i+1) (bone i+1's
// euler prefetched one bone ahead). Root -> slots 0..2. After compute each
// warp's smem region equals the packed output layout -> per-warp bulk copy.
#define EOSTR 51
#define WARP_BYTES (WSAMP * EOSTR * 4)  // 6528, multiple of 16

// One FK bone step using only the third-row vector of the accumulated
// rotation:  v' = ((v @ Rx) @ Ry) @ Rz,  pos' = pos + L * v'.
__device__ __forceinline__ void bone_step(
    float& vx, float& vy, float& vz,
    float& px, float& py, float& pz,
    float ax, float ay, float az, float Lb)
{
    float sa, ca, sb, cb, sc, cc;
    __sincosf(ax, &sa, &ca);
    __sincosf(ay, &sb, &cb);
    __sincosf(az, &sc, &cc);
    float t1 = fmaf(vy, ca,  vz * sa);
    float t2 = fmaf(vz, ca, -vy * sa);
    float u0 = fmaf(vx, cb, -t2 * sb);
    float u2 = fmaf(vx, sb,  t2 * cb);
    vx = fmaf(u0, cc,  t1 * sc);
    vy = fmaf(t1, cc, -u0 * sc);
    vz = u2;
    px = fmaf(Lb, vx, px); py = fmaf(Lb, vy, py); pz = fmaf(Lb, vz, pz);
}

#define PREFETCH(b) nx = eo[3*(b)]; ny = eo[3*(b)+1]; nz = eo[3*(b)+2]
#define STOREJ(j) eo[3*(j)] = px; eo[3*(j)+1] = py; eo[3*(j)+2] = pz
#define SHIFT() ax = nx; ay = ny; az = nz
#define RESET_ROOT() vx = 0.f; vy = 0.f; vz = 1.f; px = 0.f; py = 0.f; pz = 0.f
#define FROM_J8() vx = v8x; vy = v8y; vz = v8z; px = p8x; py = p8y; pz = p8z

__device__ __forceinline__ void fk_compute(float* eo, const float L[16]) {
    float ax = eo[0], ay = eo[1], az = eo[2];
    float nx, ny, nz;
    float vx, vy, vz, px, py, pz;
    float v8x, v8y, v8z, p8x, p8y, p8z;

    // leg 1: bones 0,1,2 -> joints 1,2,3
    PREFETCH(1); RESET_ROOT();
    bone_step(vx,vy,vz,px,py,pz, ax,ay,az, L[0]);  STOREJ(1);  SHIFT();
    PREFETCH(2);
    bone_step(vx,vy,vz,px,py,pz, ax,ay,az, L[1]);  STOREJ(2);  SHIFT();
    PREFETCH(3);
    bone_step(vx,vy,vz,px,py,pz, ax,ay,az, L[2]);  STOREJ(3);  SHIFT();

    // leg 2: bones 3,4,5 -> joints 4,5,6
    PREFETCH(4); RESET_ROOT();
    bone_step(vx,vy,vz,px,py,pz, ax,ay,az, L[3]);  STOREJ(4);  SHIFT();
    PREFETCH(5);
    bone_step(vx,vy,vz,px,py,pz, ax,ay,az, L[4]);  STOREJ(5);  SHIFT();
    PREFETCH(6);
    bone_step(vx,vy,vz,px,py,pz, ax,ay,az, L[5]);  STOREJ(6);  SHIFT();

    // spine: bone 6 (0->7), bone 7 (7->8)
    PREFETCH(7); RESET_ROOT();
    bone_step(vx,vy,vz,px,py,pz, ax,ay,az, L[6]);  STOREJ(7);  SHIFT();
    PREFETCH(8);
    bone_step(vx,vy,vz,px,py,pz, ax,ay,az, L[7]);  STOREJ(8);
    v8x = vx; v8y = vy; v8z = vz; p8x = px; p8y = py; p8z = pz;
    SHIFT();

    // head: bones 8 (8->9), 9 (9->10)
    PREFETCH(9);
    bone_step(vx,vy,vz,px,py,pz, ax,ay,az, L[8]);  STOREJ(9);  SHIFT();
    PREFETCH(10);
    bone_step(vx,vy,vz,px,py,pz, ax,ay,az, L[9]);  STOREJ(10); SHIFT();

    // arm A: bones 10,11,12 (8->11->12->13)
    PREFETCH(11); FROM_J8();
    bone_step(vx,vy,vz,px,py,pz, ax,ay,az, L[10]); STOREJ(11); SHIFT();
    PREFETCH(12);
    bone_step(vx,vy,vz,px,py,pz, ax,ay,az, L[11]); STOREJ(12); SHIFT();
    PREFETCH(13);
    bone_step(vx,vy,vz,px,py,pz, ax,ay,az, L[12]); STOREJ(13); SHIFT();

    // arm B: bones 13,14,15 (8->14->15->16)
    PREFETCH(14); FROM_J8();
    bone_step(vx,vy,vz,px,py,pz, ax,ay,az, L[13]); STOREJ(14); SHIFT();
    PREFETCH(15);
    bone_step(vx,vy,vz,px,py,pz, ax,ay,az, L[14]); STOREJ(15); SHIFT();
    bone_step(vx,vy,vz,px,py,pz, ax,ay,az, L[15]); STOREJ(16);

    eo[0] = 0.f; eo[1] = 0.f; eo[2] = 0.f;   // root joint
}

extern "C" __global__ void __launch_bounds__(TPB, 16)
fk_kernel(const float* __restrict__ euler, const float* __restrict__ blen,
          float* __restrict__ out, int N)
{
    extern __shared__ float sm[];

    const int t     = threadIdx.x;
    const int w     = t >> 5;              // warp id (0 or 1)
    const int l     = t & 31;              // lane
    const int wbase = blockIdx.x * TPB + w * WSAMP;   // first sample of this warp
    const int ns_w  = max(0, min(WSAMP, N - wbase));  // samples this warp owns
    float* s_w = sm + (w * WSAMP) * EOSTR; // this warp's smem region (16B-aligned)

    if (ns_w == 0) return;

    // ---- warp-local euler staging: 12 LDG.128 per lane (512B/instr,
    //      perfectly coalesced), phased STS into conflict-free rows ----
    {
        const float4* ge = (const float4*)(euler + (size_t)wbase * 48);
        if (ns_w == WSAMP) {
#pragma unroll
            for (int k = 0; k < 12; k++) {
                int i = l + k * 32;
                float4 v = ge[i];
                int s = i / 12, r = i - s * 12;
                float* p = s_w + s * EOSTR + r * 4;
                p[0] = v.x; p[1] = v.y; p[2] = v.z; p[3] = v.w;
            }
        } else {
            const int ne4 = ns_w * 12;
            for (int i = l; i < ne4; i += 32) {
                float4 v = ge[i];
                int s = i / 12, r = i - s * 12;
                float* p = s_w + s * EOSTR + r * 4;
                p[0] = v.x; p[1] = v.y; p[2] = v.z; p[3] = v.w;
            }
        }
    }

    // ---- bone lengths: direct per-lane float4 LDG (independent MLP) ----
    float L[16];
    if (l < ns_w) {
        const float4* gb = (const float4*)(blen + (size_t)(wbase + l) * 16);
        float4 a = gb[0], b = gb[1], c = gb[2], d = gb[3];
        L[0]=a.x;  L[1]=a.y;  L[2]=a.z;  L[3]=a.w;
        L[4]=b.x;  L[5]=b.y;  L[6]=b.z;  L[7]=b.w;
        L[8]=c.x;  L[9]=c.y;  L[10]=c.z; L[11]=c.w;
        L[12]=d.x; L[13]=d.y; L[14]=d.z; L[15]=d.w;
    }
    __syncwarp();

    // ---- per-sample FK: outputs land at natural slots -> region == out layout ----
    if (l < ns_w) {
        fk_compute(s_w + l * EOSTR, L);
    }
    __syncwarp();

    // ---- store: one async bulk copy per warp (6,528 B), issued by lane 0
    //      as soon as THIS warp finishes — no block barrier anywhere ----
    float* go = out + (size_t)wbase * 51;
    if (ns_w == WSAMP) {
        if (l == 0) {
            asm volatile("fence.proxy.async.shared::cta;" ::: "memory");
            unsigned int sa = (unsigned int)__cvta_generic_to_shared(s_w);
            asm volatile(
                "cp.async.bulk.global.shared::cta.bulk_group [%0], [%1], %2;\n"
                :: "l"(go), "r"(sa), "r"((int)WARP_BYTES) : "memory");
            asm volatile("cp.async.bulk.commit_group;" ::: "memory");
            asm volatile("cp.async.bulk.wait_group 0;" ::: "memory");
        }
    } else {
        const int nf = ns_w * 51;
        for (int g = l; g < nf; g += 32)
            go[g] = s_w[g];
    }
}

extern "C" void kernel_launch(void* const* d_in, const int* in_sizes, int n_in,
                              void* d_out, int out_size)
{
    const float* euler = (const float*)d_in[0];   // (N,16,3) f32
    const float* blen  = (const float*)d_in[1];   // (N,16,1) f32
    float* out = (float*)d_out;                   // (N,17,3) f32

    const int N = in_sizes[0] / 48;
    const int grid = (N + TPB - 1) / TPB;
    const size_t smem = (size_t)TPB * EOSTR * sizeof(float); // 13,056 B -> 16 blocks/SM

    cudaFuncSetAttribute(fk_kernel, cudaFuncAttributeMaxDynamicSharedMemorySize, (int)smem);
    cudaFuncSetAttribute(fk_kernel, cudaFuncAttributePreferredSharedMemoryCarveout,
                         cudaSharedmemCarveoutMaxShared);
    fk_kernel<<<grid, TPB, smem>>>(euler, blen, out, N);
}